// round 5
// baseline (speedup 1.0000x reference)
#include <cuda_runtime.h>
#include <cstdint>

// C4ByteNibbleVM — integer semantics of the one-hot "neural VM":
//   s = a + b (u32, little-endian ripple carry), out_byte[i] = s_byte[i] ^ a_byte[i],
// output as exact one-hot [B,4,256] f32 (reference softmax is one-hot to ~1e-7).
//
// R4 -> R5: same 4-stage x 256B early-exit probing (expected input read
// 640B/row), but register-squeezed: resolved bytes accumulate directly into
// av/bv (no pos[8] array). Target <=36 regs so __launch_bounds__(256,7) gives
// 56 warps/SM to hide the serialized probe epochs (R4 was 48 theor / 41 ach).

__global__ __launch_bounds__(256, 7) void c4_vm_kernel(
    const float* __restrict__ a,
    const float* __restrict__ b,
    float* __restrict__ out,
    int nwords)
{
    const int warp = (blockIdx.x * (blockDim.x >> 5)) + (threadIdx.x >> 5);
    const int lane = threadIdx.x & 31;
    if (warp >= nwords) return;

    // Row = 256 floats = 128 float2. Word block = 4 rows = 512 float2.
    const float2* __restrict__ pa =
        reinterpret_cast<const float2*>(a) + (size_t)warp * 512 + lane;
    const float2* __restrict__ pb =
        reinterpret_cast<const float2*>(b) + (size_t)warp * 512 + lane;

    unsigned av = 0, bv = 0;
    unsigned unres = 0xffu;                     // bit r: row r not yet located

#pragma unroll
    for (int s = 0; s < 4; s++) {               // stage s covers floats [s*64, s*64+64)
        if (unres) {                            // warp-uniform
            float2 v[8];
#pragma unroll
            for (int r = 0; r < 8; r++) {
                if (unres & (1u << r)) {        // warp-uniform, predicated load
                    const float2* p = (r < 4) ? pa : pb;
                    v[r] = __ldcs(p + (r & 3) * 128 + s * 32);
                }
            }
#pragma unroll
            for (int r = 0; r < 8; r++) {
                if (unres & (1u << r)) {        // warp-uniform
                    const unsigned bx = __ballot_sync(0xffffffffu, v[r].x > 0.5f);
                    const unsigned by = __ballot_sync(0xffffffffu, v[r].y > 0.5f);
                    const unsigned cb = bx | by;
                    if (cb) {                   // warp-uniform
                        const unsigned p =
                            s * 64 + ((__ffs(cb) - 1) << 1) + (bx ? 0u : 1u);
                        if (r < 4) av |= p << (8 * r);
                        else       bv |= p << (8 * (r - 4));
                        unres &= ~(1u << r);
                    }
                }
            }
        }
    }

    // ---- Integer VM op ----
    const unsigned o = (av + bv) ^ av;

    // ---- One-hot output: 4 rows x 1KB, coalesced 128-bit stores ----
    float4* __restrict__ o4 = reinterpret_cast<float4*>(out) + (size_t)warp * 256;

#pragma unroll
    for (int i = 0; i < 4; i++) {
        const unsigned ob = (o >> (8 * i)) & 0xffu;
        const int q = ob >> 2;                  // which float4 (0..63)
        const int e = ob & 3;                   // element within float4
        float4 z0 = make_float4(0.f, 0.f, 0.f, 0.f);
        float4 z1 = make_float4(0.f, 0.f, 0.f, 0.f);
        if (q == lane)      (&z0.x)[e] = 1.0f;
        if (q == lane + 32) (&z1.x)[e] = 1.0f;
        o4[i * 64 + lane]      = z0;
        o4[i * 64 + 32 + lane] = z1;
    }
}

extern "C" void kernel_launch(void* const* d_in, const int* in_sizes, int n_in,
                              void* d_out, int out_size)
{
    const float* a = (const float*)d_in[0];   // a_bytes [B,4,256]
    const float* b = (const float*)d_in[1];   // b_bytes [B,4,256]
    float* out = (float*)d_out;               // [B,4,256]

    const int nwords = in_sizes[0] / 1024;    // B
    const int warps_per_block = 8;            // 256 threads
    const int blocks = (nwords + warps_per_block - 1) / warps_per_block;

    c4_vm_kernel<<<blocks, 256>>>(a, b, out, nwords);
}

// round 6
// speedup vs baseline: 1.0420x; 1.0420x over previous
#include <cuda_runtime.h>
#include <cstdint>

// C4ByteNibbleVM — integer semantics of the one-hot "neural VM":
//   s = a + b (u32, little-endian ripple carry), out_byte[i] = s_byte[i] ^ a_byte[i],
// output as exact one-hot [B,4,256] f32 (reference softmax is one-hot to ~1e-7).
//
// R5 -> R6: revert the over-squeeze (R5 spilled; L1% jumped, DRAM% fell).
// Back to R4's 4-stage x 256B early-exit probing, but each warp now handles
// TWO words with interleaved stages: every probe epoch carries both words'
// unresolved rows, doubling bytes-in-flight in the thin late stages without
// adding dependent epochs. Peak live set ~50 regs -> __launch_bounds__(256,5).

__global__ __launch_bounds__(256, 5) void c4_vm_kernel(
    const float* __restrict__ a,
    const float* __restrict__ b,
    float* __restrict__ out,
    int nwords)
{
    const int warp = (blockIdx.x * (blockDim.x >> 5)) + (threadIdx.x >> 5);
    const int lane = threadIdx.x & 31;
    const int w0 = warp * 2;                    // this warp's first word
    if (w0 >= nwords) return;
    const bool has2 = (w0 + 1) < nwords;

    // Row = 256 floats = 128 float2. Word block = 4 rows = 512 float2.
    const float2* __restrict__ pa =
        reinterpret_cast<const float2*>(a) + (size_t)w0 * 512 + lane;
    const float2* __restrict__ pb =
        reinterpret_cast<const float2*>(b) + (size_t)w0 * 512 + lane;

    unsigned av[2] = {0, 0}, bv[2] = {0, 0};
    unsigned unres[2];
    unres[0] = 0xffu;
    unres[1] = has2 ? 0xffu : 0u;

#pragma unroll
    for (int s = 0; s < 4; s++) {               // stage s covers floats [s*64, s*64+64)
        if (unres[0] | unres[1]) {              // warp-uniform
            float2 v[2][8];
            // ---- batched loads: both words' unresolved rows ----
#pragma unroll
            for (int t = 0; t < 2; t++) {
#pragma unroll
                for (int r = 0; r < 8; r++) {
                    if (unres[t] & (1u << r)) { // warp-uniform, predicated load
                        const float2* p = (r < 4) ? pa : pb;
                        v[t][r] = __ldcs(p + t * 512 + (r & 3) * 128 + s * 32);
                    }
                }
            }
            // ---- decode both words ----
#pragma unroll
            for (int t = 0; t < 2; t++) {
#pragma unroll
                for (int r = 0; r < 8; r++) {
                    if (unres[t] & (1u << r)) { // warp-uniform
                        const unsigned bx = __ballot_sync(0xffffffffu, v[t][r].x > 0.5f);
                        const unsigned by = __ballot_sync(0xffffffffu, v[t][r].y > 0.5f);
                        const unsigned cb = bx | by;
                        if (cb) {               // warp-uniform
                            const unsigned p =
                                s * 64 + ((__ffs(cb) - 1) << 1) + (bx ? 0u : 1u);
                            if (r < 4) av[t] |= p << (8 * r);
                            else       bv[t] |= p << (8 * (r - 4));
                            unres[t] &= ~(1u << r);
                        }
                    }
                }
            }
        }
    }

    // ---- Integer VM op + one-hot output for both words ----
#pragma unroll
    for (int t = 0; t < 2; t++) {
        if (t == 1 && !has2) break;
        const unsigned o = (av[t] + bv[t]) ^ av[t];
        float4* __restrict__ o4 =
            reinterpret_cast<float4*>(out) + (size_t)(w0 + t) * 256;
#pragma unroll
        for (int i = 0; i < 4; i++) {
            const unsigned ob = (o >> (8 * i)) & 0xffu;
            const int q = ob >> 2;              // which float4 (0..63)
            const int e = ob & 3;               // element within float4
            float4 z0 = make_float4(0.f, 0.f, 0.f, 0.f);
            float4 z1 = make_float4(0.f, 0.f, 0.f, 0.f);
            if (q == lane)      (&z0.x)[e] = 1.0f;
            if (q == lane + 32) (&z1.x)[e] = 1.0f;
            o4[i * 64 + lane]      = z0;
            o4[i * 64 + 32 + lane] = z1;
        }
    }
}

extern "C" void kernel_launch(void* const* d_in, const int* in_sizes, int n_in,
                              void* d_out, int out_size)
{
    const float* a = (const float*)d_in[0];   // a_bytes [B,4,256]
    const float* b = (const float*)d_in[1];   // b_bytes [B,4,256]
    float* out = (float*)d_out;               // [B,4,256]

    const int nwords = in_sizes[0] / 1024;    // B
    const int words_per_block = 16;           // 8 warps x 2 words
    const int blocks = (nwords + words_per_block - 1) / words_per_block;

    c4_vm_kernel<<<blocks, 256>>>(a, b, out, nwords);
}

// round 8
// speedup vs baseline: 1.1136x; 1.0687x over previous
#include <cuda_runtime.h>
#include <cstdint>

// C4ByteNibbleVM — integer semantics of the one-hot "neural VM":
//   s = a + b (u32, little-endian ripple carry), out_byte[i] = s_byte[i] ^ a_byte[i],
// output as exact one-hot [B,4,256] f32 (reference softmax is one-hot to ~1e-7).
//
// R6 -> R7: back to R4's single-word, 4-stage x 256B early-exit structure
// (best so far), with a leaner probe/decode:
//  * one float4 load covers TWO rows per stage (16 lanes x 16B each), per-lane
//    predicated so resolved rows fetch nothing (expected read still 640B/row)
//  * decode = 3 ballots per row-pair (hit, bit0, bit1) + ffs; no REDUX
//  * streaming stores (__stcs)

__global__ __launch_bounds__(256, 6) void c4_vm_kernel(
    const float* __restrict__ a,
    const float* __restrict__ b,
    float* __restrict__ out,
    int nwords)
{
    const int warp = (blockIdx.x * (blockDim.x >> 5)) + (threadIdx.x >> 5);
    const int lane = threadIdx.x & 31;
    if (warp >= nwords) return;

    const int hl = lane >> 4;                   // which row of the pair this lane probes
    const int lr = lane & 15;                   // float4 slot within the 256B chunk

    // Row = 64 float4; word block = 4 rows = 256 float4 per side.
    const float4* __restrict__ a4 = reinterpret_cast<const float4*>(a) + (size_t)warp * 256;
    const float4* __restrict__ b4 = reinterpret_cast<const float4*>(b) + (size_t)warp * 256;

    unsigned av = 0, bv = 0;
    unsigned unres = 0xffu;                     // bit gr: global row gr (0-3 = a, 4-7 = b) unresolved

#pragma unroll
    for (int s = 0; s < 4; s++) {               // stage s covers floats [s*64, s*64+64) of each row
        if (unres) {                            // warp-uniform
            float4 v[4];
            // ---- 4 paired loads: pair p covers rows {(p&1)*2, (p&1)*2+1} of side p>>1 ----
#pragma unroll
            for (int p = 0; p < 4; p++) {
                const int rp = (p & 1) * 2 + hl;        // row within side (lane-dependent)
                const int gr = (p >> 1) * 4 + rp;       // global row bit
                v[p] = make_float4(0.f, 0.f, 0.f, 0.f);
                if ((unres >> gr) & 1u) {               // per-lane predicate
                    const float4* base = (p < 2) ? a4 : b4;
                    v[p] = __ldcs(base + rp * 64 + s * 16 + lr);
                }
            }
            // ---- decode: 3 ballots per pair ----
#pragma unroll
            for (int p = 0; p < 4; p++) {
                const float4 vv = v[p];
                const bool hx = vv.x > 0.5f, hy = vv.y > 0.5f;
                const bool hz = vv.z > 0.5f, hw = vv.w > 0.5f;
                const unsigned bhit = __ballot_sync(0xffffffffu, hx | hy | hz | hw);
                const unsigned bb0  = __ballot_sync(0xffffffffu, hy | hw);   // index bit0 (y or w)
                const unsigned bb1  = __ballot_sync(0xffffffffu, hz | hw);   // index bit1 (z or w)
#pragma unroll
                for (int h = 0; h < 2; h++) {
                    const int rp2 = (p & 1) * 2 + h;
                    const int gr2 = (p >> 1) * 4 + rp2;
                    if ((unres >> gr2) & 1u) {          // warp-uniform
                        const unsigned hwm = (bhit >> (16 * h)) & 0xffffu;
                        if (hwm) {                      // warp-uniform
                            const int win = __ffs(hwm) - 1;     // lane-slot within chunk (0-15)
                            const int wa  = win + 16 * h;       // absolute ballot bit
                            const unsigned e = (((bb1 >> wa) & 1u) << 1) | ((bb0 >> wa) & 1u);
                            const unsigned pos = s * 64 + win * 4 + e;
                            if (p < 2) av |= pos << (8 * rp2);
                            else       bv |= pos << (8 * rp2);
                            unres &= ~(1u << gr2);
                        }
                    }
                }
            }
        }
    }

    // ---- Integer VM op ----
    const unsigned o = (av + bv) ^ av;

    // ---- One-hot output: 4 rows x 1KB, coalesced streaming 128-bit stores ----
    float4* __restrict__ o4 = reinterpret_cast<float4*>(out) + (size_t)warp * 256;

#pragma unroll
    for (int i = 0; i < 4; i++) {
        const unsigned ob = (o >> (8 * i)) & 0xffu;
        const int q = ob >> 2;                  // which float4 (0..63)
        const int e = ob & 3;                   // element within float4
        float4 z0 = make_float4(0.f, 0.f, 0.f, 0.f);
        float4 z1 = make_float4(0.f, 0.f, 0.f, 0.f);
        if (q == lane)      (&z0.x)[e] = 1.0f;
        if (q == lane + 32) (&z1.x)[e] = 1.0f;
        __stcs(&o4[i * 64 + lane], z0);
        __stcs(&o4[i * 64 + 32 + lane], z1);
    }
}

extern "C" void kernel_launch(void* const* d_in, const int* in_sizes, int n_in,
                              void* d_out, int out_size)
{
    const float* a = (const float*)d_in[0];   // a_bytes [B,4,256]
    const float* b = (const float*)d_in[1];   // b_bytes [B,4,256]
    float* out = (float*)d_out;               // [B,4,256]

    const int nwords = in_sizes[0] / 1024;    // B
    const int warps_per_block = 8;            // 256 threads
    const int blocks = (nwords + warps_per_block - 1) / warps_per_block;

    c4_vm_kernel<<<blocks, 256>>>(a, b, out, nwords);
}